// round 10
// baseline (speedup 1.0000x reference)
#include <cuda_runtime.h>

#define GW      1024
#define GH      1024
#define W_OUT   4096
#define H_OUT   4096
#define NCH     4
#define GPLANE  (GH * GW)          // 1048576
#define OPLANE  (H_OUT * W_OUT)    // 16777216
#define TILE    1024               // period of the output in both axes

// Faithful fp32 replication of the reference coordinate chain:
//   f = (v - 511.5)/511.5 ; t = ((f + 1) * 0.5) * 1023 ; clip ; floor
__device__ __forceinline__ void axis_entry(int v, int* p0, float* pw) {
    float fv = __fadd_rn((float)v, -511.5f);
    float f  = __fdiv_rn(fv, 511.5f);
    float t  = __fmul_rn(__fmul_rn(__fadd_rn(f, 1.0f), 0.5f), 1023.0f);
    t = fminf(fmaxf(t, 0.0f), 1023.0f);
    float f0 = floorf(t);
    *p0 = (int)f0;
    *pw = __fadd_rn(t, -f0);
}

// One thread per UNIQUE pixel (1024x1024), 4096 CTAs x 256 threads.
// 16 L2-resident gathers + 4-channel bilinear, then 64 coalesced
// WRITE-THROUGH stores (16 periodic replicas x 4 channels).
// __stwt keeps the 256MB write stream from building dirty L2 lines:
// DRAM drains in-order and the 16MB grid stays L2-resident.
__global__ void __launch_bounds__(256) sample_rep_wt_kernel(const float* __restrict__ grid,
                                                            const int* __restrict__ cs,
                                                            float* __restrict__ out) {
    const int t = blockIdx.x * blockDim.x + threadIdx.x;   // 0 .. 1048575
    const int x = t & (TILE - 1);
    const int y = t >> 10;

    const int cs0 = cs[0];
    const int cs1 = cs[1];

    int x0; float wx;
    axis_entry((cs0 + x) & (GW - 1), &x0, &wx);
    int y0; float wy;
    axis_entry((cs1 + y) & (GH - 1), &y0, &wy);   // warp-uniform

    const int   x1  = min(x0 + 1, GW - 1);
    const int   y1  = min(y0 + 1, GH - 1);
    const float omx = 1.0f - wx;
    const float omy = 1.0f - wy;

    const float* r0 = grid + y0 * GW;
    const float* r1 = grid + y1 * GW;

    float v[NCH];
#pragma unroll
    for (int c = 0; c < NCH; ++c) {
        const float* p0 = r0 + c * GPLANE;
        const float* p1 = r1 + c * GPLANE;
        float v00 = __ldg(p0 + x0);
        float v01 = __ldg(p0 + x1);
        float v10 = __ldg(p1 + x0);
        float v11 = __ldg(p1 + x1);
        float top = v00 * omx + v01 * wx;
        float bot = v10 * omx + v11 * wx;
        v[c] = top * omy + bot * wy;
    }

    const int obase = y * W_OUT + x;
#pragma unroll
    for (int c = 0; c < NCH; ++c) {
        float* po = out + c * OPLANE + obase;
        const float val = v[c];
#pragma unroll
        for (int dy = 0; dy < 4; ++dy) {
#pragma unroll
            for (int dx = 0; dx < 4; ++dx) {
                __stwt(po + dy * (TILE * W_OUT) + dx * TILE, val);
            }
        }
    }
}

extern "C" void kernel_launch(void* const* d_in, const int* in_sizes, int n_in,
                              void* d_out, int out_size) {
    const float* grid = (const float*)d_in[0];
    const int*   cs   = (const int*)d_in[1];
    float*       out  = (float*)d_out;

    sample_rep_wt_kernel<<<(TILE * TILE) / 256, 256>>>(grid, cs, out);
}